// round 4
// baseline (speedup 1.0000x reference)
#include <cuda_runtime.h>
#include <math.h>

#define Tn 512
#define Bn 64
#define In 512
#define Hn 1024
#define G4n 4096
#define KEEP 0.9f
#define NBLK 128

// Scratch: precomputed input-gates for all timesteps (T*B x 4H fp32 = 512MB)
__device__ float g_pre[(long long)Tn * Bn * G4n];
// Double-buffered hidden state
__device__ float g_hb[2][Bn * Hn];
// Grid barrier state (zero-initialized; g_gen monotonic across graph replays)
__device__ unsigned g_count;
__device__ unsigned g_gen;

__device__ __forceinline__ float sigf(float x) { return 1.0f / (1.0f + expf(-x)); }

__device__ __forceinline__ void grid_sync() {
    __syncthreads();
    if (threadIdx.x == 0) {
        __threadfence();
        volatile unsigned* vgen = &g_gen;
        unsigned gen = *vgen;
        if (atomicAdd(&g_count, 1u) == NBLK - 1) {
            g_count = 0u;
            __threadfence();
            atomicAdd(&g_gen, 1u);
        } else {
            while (*vgen == gen) { __nanosleep(64); }
        }
    }
    __syncthreads();
}

// ---------------------------------------------------------------------------
// Kernel 1: G = (0.9*x) @ W_ih^T + (b_ih + b_hh)   for all T*B rows.
// M=32768, N=4096, K=512. 64x64 block tile, 4x4 per thread, double-buffered smem.
// ---------------------------------------------------------------------------
__global__ void __launch_bounds__(256) pre_gemm_kernel(
    const float* __restrict__ x, const float* __restrict__ Wih,
    const float* __restrict__ bih, const float* __restrict__ bhh)
{
    __shared__ float As[2][16][64];
    __shared__ float Bs[2][16][64];
    const int tid = threadIdx.x;
    const int bm = blockIdx.y << 6;   // row tile base in [0, 32768)
    const int bn = blockIdx.x << 6;   // col tile base in [0, 4096)
    const int lm = tid >> 2;          // 0..63 (row within tile for staging)
    const int lk = (tid & 3) << 2;    // 0,4,8,12 (k within chunk for staging)
    const int ty = tid >> 4;          // 0..15
    const int tx = tid & 15;          // 0..15

    const float* xrow = x + (size_t)(bm + lm) * In + lk;
    const float* wrow = Wih + (size_t)(bn + lm) * In + lk;

    // Stage chunk 0
    {
        float4 av = *(const float4*)xrow;
        float4 wv = *(const float4*)wrow;
        As[0][lk + 0][lm] = av.x * KEEP; As[0][lk + 1][lm] = av.y * KEEP;
        As[0][lk + 2][lm] = av.z * KEEP; As[0][lk + 3][lm] = av.w * KEEP;
        Bs[0][lk + 0][lm] = wv.x; Bs[0][lk + 1][lm] = wv.y;
        Bs[0][lk + 2][lm] = wv.z; Bs[0][lk + 3][lm] = wv.w;
    }
    __syncthreads();

    float acc[4][4];
#pragma unroll
    for (int i = 0; i < 4; i++)
#pragma unroll
        for (int j = 0; j < 4; j++) acc[i][j] = 0.0f;

#pragma unroll 1
    for (int ch = 0; ch < 32; ch++) {
        const int buf = ch & 1;
        float4 a2, w2;
        if (ch < 31) {
            a2 = *(const float4*)(xrow + (ch + 1) * 16);
            w2 = *(const float4*)(wrow + (ch + 1) * 16);
        }
#pragma unroll
        for (int k = 0; k < 16; k++) {
            float4 a = *(const float4*)&As[buf][k][ty << 2];
            float4 b = *(const float4*)&Bs[buf][k][tx << 2];
            acc[0][0] += a.x * b.x; acc[0][1] += a.x * b.y; acc[0][2] += a.x * b.z; acc[0][3] += a.x * b.w;
            acc[1][0] += a.y * b.x; acc[1][1] += a.y * b.y; acc[1][2] += a.y * b.z; acc[1][3] += a.y * b.w;
            acc[2][0] += a.z * b.x; acc[2][1] += a.z * b.y; acc[2][2] += a.z * b.z; acc[2][3] += a.z * b.w;
            acc[3][0] += a.w * b.x; acc[3][1] += a.w * b.y; acc[3][2] += a.w * b.z; acc[3][3] += a.w * b.w;
        }
        if (ch < 31) {
            const int nb = buf ^ 1;
            As[nb][lk + 0][lm] = a2.x * KEEP; As[nb][lk + 1][lm] = a2.y * KEEP;
            As[nb][lk + 2][lm] = a2.z * KEEP; As[nb][lk + 3][lm] = a2.w * KEEP;
            Bs[nb][lk + 0][lm] = w2.x; Bs[nb][lk + 1][lm] = w2.y;
            Bs[nb][lk + 2][lm] = w2.z; Bs[nb][lk + 3][lm] = w2.w;
        }
        __syncthreads();
    }

    float bi[4];
#pragma unroll
    for (int j = 0; j < 4; j++) {
        int col = bn + (tx << 2) + j;
        bi[j] = bih[col] + bhh[col];
    }
#pragma unroll
    for (int i = 0; i < 4; i++) {
        float4 o;
        o.x = acc[i][0] + bi[0];
        o.y = acc[i][1] + bi[1];
        o.z = acc[i][2] + bi[2];
        o.w = acc[i][3] + bi[3];
        *(float4*)&g_pre[(size_t)(bm + (ty << 2) + i) * G4n + bn + (tx << 2)] = o;
    }
}

// ---------------------------------------------------------------------------
// Kernel 2: persistent LSTM recurrence. 128 blocks (all resident), one grid
// barrier per timestep. Block = (b_half: 32 rows) x (n_slice: 16 hidden units).
// Each thread computes 2 batch rows x 1 hidden unit -> holds i/f/g/o for its
// cells in registers; c-state lives in registers for all 512 steps.
// ---------------------------------------------------------------------------
__global__ void __launch_bounds__(256) lstm_seq_kernel(
    const float* __restrict__ Whh, float* __restrict__ out)
{
    __shared__ float hs[2][32][34];   // [buf][k][b_local], padded row
    __shared__ float ws[2][32][64];   // [buf][k][n_local*4 + gate]
    const int tid = threadIdx.x;
    const int blk = blockIdx.x;
    const int n0 = (blk & 63) << 4;   // hidden-unit slice base (16 wide)
    const int b0 = (blk >> 6) << 5;   // batch half base (0 or 32)
    const int ty = tid >> 4;          // 0..15
    const int tx = tid & 15;          // 0..15
    // staging indices
    const int hm = tid >> 3;          // 0..31 (batch row for h staging)
    const int hk = (tid & 7) << 2;    // 0..28 (k for h staging, float4)
    const int wj = tid >> 2;          // 0..63 (gate-col for W staging)
    const int wk = (tid & 3) << 2;    // 0,4,8,12
    const int wg = wj >> 4;           // gate 0..3
    const int wn = wj & 15;           // n_local
    const int wcol = (wn << 2) + wg;  // smem column in gate-interleaved layout
    const float* wrow = Whh + (size_t)(wg * Hn + n0 + wn) * Hn;

    const int r0 = b0 + (ty << 1);    // this thread's first batch row
    const int nn = n0 + tx;           // this thread's hidden unit

    // zero-init h buffer 0 (owned slice) and c state
    g_hb[0][(size_t)(r0 + 0) * Hn + nn] = 0.0f;
    g_hb[0][(size_t)(r0 + 1) * Hn + nn] = 0.0f;
    float c0 = 0.0f, c1 = 0.0f;
    grid_sync();

#pragma unroll 1
    for (int t = 0; t < Tn; t++) {
        const float* hr = g_hb[t & 1];
        float* hw = g_hb[(t + 1) & 1];
        const float* hrow = hr + (size_t)(b0 + hm) * Hn;

        // init accumulators from precomputed input gates (+bias)
        float acc0[4], acc1[4];
        {
            const float* p = g_pre + ((size_t)t * Bn + r0) * G4n + nn;
#pragma unroll
            for (int g = 0; g < 4; g++) {
                acc0[g] = p[g * Hn];
                acc1[g] = p[G4n + g * Hn];
            }
        }

        // stage k-chunk 0 (32 k's)
        {
            float4 hv = __ldcg((const float4*)(hrow + hk));
            float4 w0 = *(const float4*)(wrow + wk);
            float4 w1 = *(const float4*)(wrow + wk + 16);
            hs[0][hk + 0][hm] = hv.x; hs[0][hk + 1][hm] = hv.y;
            hs[0][hk + 2][hm] = hv.z; hs[0][hk + 3][hm] = hv.w;
            ws[0][wk + 0][wcol] = w0.x; ws[0][wk + 1][wcol] = w0.y;
            ws[0][wk + 2][wcol] = w0.z; ws[0][wk + 3][wcol] = w0.w;
            ws[0][wk + 16][wcol] = w1.x; ws[0][wk + 17][wcol] = w1.y;
            ws[0][wk + 18][wcol] = w1.z; ws[0][wk + 19][wcol] = w1.w;
        }
        __syncthreads();

#pragma unroll 1
        for (int ch = 0; ch < 32; ch++) {
            const int buf = ch & 1;
            float4 hv2, w02, w12;
            if (ch < 31) {
                const int k0 = (ch + 1) << 5;
                hv2 = __ldcg((const float4*)(hrow + k0 + hk));
                w02 = *(const float4*)(wrow + k0 + wk);
                w12 = *(const float4*)(wrow + k0 + wk + 16);
            }
#pragma unroll
            for (int k = 0; k < 32; k++) {
                float2 a = *(const float2*)&hs[buf][k][ty << 1];
                float4 b = *(const float4*)&ws[buf][k][tx << 2];
                acc0[0] += a.x * b.x; acc0[1] += a.x * b.y;
                acc0[2] += a.x * b.z; acc0[3] += a.x * b.w;
                acc1[0] += a.y * b.x; acc1[1] += a.y * b.y;
                acc1[2] += a.y * b.z; acc1[3] += a.y * b.w;
            }
            if (ch < 31) {
                const int nb = buf ^ 1;
                hs[nb][hk + 0][hm] = hv2.x; hs[nb][hk + 1][hm] = hv2.y;
                hs[nb][hk + 2][hm] = hv2.z; hs[nb][hk + 3][hm] = hv2.w;
                ws[nb][wk + 0][wcol] = w02.x; ws[nb][wk + 1][wcol] = w02.y;
                ws[nb][wk + 2][wcol] = w02.z; ws[nb][wk + 3][wcol] = w02.w;
                ws[nb][wk + 16][wcol] = w12.x; ws[nb][wk + 17][wcol] = w12.y;
                ws[nb][wk + 18][wcol] = w12.z; ws[nb][wk + 19][wcol] = w12.w;
            }
            __syncthreads();
        }

        // LSTM cell update (all gates for (b, n) are in this thread's regs)
#pragma unroll
        for (int i = 0; i < 2; i++) {
            const float gi = i ? acc1[0] : acc0[0];
            const float gf = i ? acc1[1] : acc0[1];
            const float gg = i ? acc1[2] : acc0[2];
            const float go = i ? acc1[3] : acc0[3];
            const float cprev = i ? c1 : c0;
            const float ig = sigf(gi);
            const float fg = sigf(gf);
            const float gv = tanhf(gg);
            const float og = sigf(go);
            const float cn = fg * cprev + ig * gv;
            const float hval = og * tanhf(cn) * KEEP;
            if (i) c1 = cn; else c0 = cn;
            const int b = r0 + i;
            __stcg(hw + (size_t)b * Hn + nn, hval);
            out[((size_t)t * Bn + b) * Hn + nn] = hval;
            if (t == Tn - 1) {
                out[(size_t)Tn * Bn * Hn + (size_t)b * Hn + nn] = hval;                       // h_last
                out[(size_t)Tn * Bn * Hn + (size_t)Bn * Hn + (size_t)b * Hn + nn] = cn;       // c_last
            }
        }
        grid_sync();
    }
}

extern "C" void kernel_launch(void* const* d_in, const int* in_sizes, int n_in,
                              void* d_out, int out_size) {
    const float* x   = (const float*)d_in[0];
    const float* Wih = (const float*)d_in[1];
    const float* Whh = (const float*)d_in[2];
    const float* bih = (const float*)d_in[3];
    const float* bhh = (const float*)d_in[4];
    float* out = (float*)d_out;

    dim3 g1(G4n / 64, (Tn * Bn) / 64);   // 64 x 512 blocks
    pre_gemm_kernel<<<g1, 256>>>(x, Wih, bih, bhh);
    lstm_seq_kernel<<<NBLK, 256>>>(Whh, out);
}

// round 6
// speedup vs baseline: 1.2136x; 1.2136x over previous
#include <cuda_runtime.h>
#include <math.h>

#define Tn 512
#define Bn 64
#define In 512
#define Hn 1024
#define G4n 4096
#define KEEP 0.9f
#define NBLK 128
#define KHALF 512

typedef unsigned long long ull;

// Scratch: precomputed input-gates for all timesteps (T*B x 4H fp32 = 512MB)
__device__ float g_pre[(long long)Tn * Bn * G4n];
// Double-buffered hidden state
__device__ float g_hb[2][Bn * Hn];
// K-split partial exchange: 64 block-pairs x 256 threads x 8 packed ull (64B/thread)
__device__ ull g_part[64][256 * 8];
__device__ unsigned g_flag[64];
// Grid barrier state (g_gen monotonic across graph replays)
__device__ unsigned g_count;
__device__ unsigned g_gen;

__device__ __forceinline__ float sigf(float x) { return 1.0f / (1.0f + expf(-x)); }

// ---- packed f32x2 helpers (Blackwell FFMA2 path) ----
__device__ __forceinline__ ull pk2(float v) {
    ull r; asm("mov.b64 %0, {%1, %1};" : "=l"(r) : "f"(v)); return r;
}
__device__ __forceinline__ ull pkab(float a, float b) {
    ull r; asm("mov.b64 %0, {%1, %2};" : "=l"(r) : "f"(a), "f"(b)); return r;
}
__device__ __forceinline__ void unpk(ull v, float& lo, float& hi) {
    asm("mov.b64 {%0, %1}, %2;" : "=f"(lo), "=f"(hi) : "l"(v));
}
__device__ __forceinline__ void fma2(ull& acc, ull a, ull b) {
    asm("fma.rn.f32x2 %0, %1, %2, %0;" : "+l"(acc) : "l"(a), "l"(b));
}
__device__ __forceinline__ void add2(ull& a, ull b) {
    asm("add.rn.f32x2 %0, %0, %1;" : "+l"(a) : "l"(b));
}
__device__ __forceinline__ void st2cg(ull* p, ull a, ull b) {
    asm volatile("st.global.cg.v2.u64 [%0], {%1, %2};" :: "l"(p), "l"(a), "l"(b) : "memory");
}
__device__ __forceinline__ void ld2cg(const ull* p, ull& a, ull& b) {
    asm volatile("ld.global.cg.v2.u64 {%0, %1}, [%2];" : "=l"(a), "=l"(b) : "l"(p) : "memory");
}

__device__ __forceinline__ void grid_sync() {
    __syncthreads();
    if (threadIdx.x == 0) {
        __threadfence();
        volatile unsigned* vgen = &g_gen;
        unsigned gen = *vgen;
        if (atomicAdd(&g_count, 1u) == NBLK - 1) {
            g_count = 0u;
            __threadfence();
            atomicAdd(&g_gen, 1u);
        } else {
            while (*vgen == gen) { __nanosleep(64); }
        }
    }
    __syncthreads();
}

// ---------------------------------------------------------------------------
// Kernel 1: G = (0.9*x) @ W_ih^T + (b_ih + b_hh), M=32768 N=4096 K=512.
// 64x64 tile, 4x4 per thread, packed FFMA2 inner loop.
// ---------------------------------------------------------------------------
__global__ void __launch_bounds__(256) pre_gemm_kernel(
    const float* __restrict__ x, const float* __restrict__ Wih,
    const float* __restrict__ bih, const float* __restrict__ bhh)
{
    __shared__ __align__(16) float As[2][16][64];
    __shared__ __align__(16) float Bs[2][16][64];
    const int tid = threadIdx.x;
    const int bm = blockIdx.y << 6;
    const int bn = blockIdx.x << 6;
    const int lm = tid >> 2;
    const int lk = (tid & 3) << 2;
    const int ty = tid >> 4;
    const int tx = tid & 15;

    const float* xrow = x + (size_t)(bm + lm) * In + lk;
    const float* wrow = Wih + (size_t)(bn + lm) * In + lk;

    {
        float4 av = *(const float4*)xrow;
        float4 wv = *(const float4*)wrow;
        As[0][lk + 0][lm] = av.x * KEEP; As[0][lk + 1][lm] = av.y * KEEP;
        As[0][lk + 2][lm] = av.z * KEEP; As[0][lk + 3][lm] = av.w * KEEP;
        Bs[0][lk + 0][lm] = wv.x; Bs[0][lk + 1][lm] = wv.y;
        Bs[0][lk + 2][lm] = wv.z; Bs[0][lk + 3][lm] = wv.w;
    }
    __syncthreads();

    ull accp[4][2];
#pragma unroll
    for (int i = 0; i < 4; i++) { accp[i][0] = 0ull; accp[i][1] = 0ull; }

#pragma unroll 1
    for (int ch = 0; ch < 32; ch++) {
        const int buf = ch & 1;
        float4 a2, w2;
        if (ch < 31) {
            a2 = *(const float4*)(xrow + (ch + 1) * 16);
            w2 = *(const float4*)(wrow + (ch + 1) * 16);
        }
#pragma unroll
        for (int k = 0; k < 16; k++) {
            float4 a = *(const float4*)&As[buf][k][ty << 2];
            ulonglong2 w = *(const ulonglong2*)&Bs[buf][k][tx << 2];
            ull a0 = pk2(a.x), a1 = pk2(a.y), a2p = pk2(a.z), a3 = pk2(a.w);
            fma2(accp[0][0], a0, w.x); fma2(accp[0][1], a0, w.y);
            fma2(accp[1][0], a1, w.x); fma2(accp[1][1], a1, w.y);
            fma2(accp[2][0], a2p, w.x); fma2(accp[2][1], a2p, w.y);
            fma2(accp[3][0], a3, w.x); fma2(accp[3][1], a3, w.y);
        }
        if (ch < 31) {
            const int nb = buf ^ 1;
            As[nb][lk + 0][lm] = a2.x * KEEP; As[nb][lk + 1][lm] = a2.y * KEEP;
            As[nb][lk + 2][lm] = a2.z * KEEP; As[nb][lk + 3][lm] = a2.w * KEEP;
            Bs[nb][lk + 0][lm] = w2.x; Bs[nb][lk + 1][lm] = w2.y;
            Bs[nb][lk + 2][lm] = w2.z; Bs[nb][lk + 3][lm] = w2.w;
        }
        __syncthreads();
    }

    float bi[4];
#pragma unroll
    for (int j = 0; j < 4; j++) {
        int col = bn + (tx << 2) + j;
        bi[j] = bih[col] + bhh[col];
    }
#pragma unroll
    for (int i = 0; i < 4; i++) {
        float v0, v1, v2, v3;
        unpk(accp[i][0], v0, v1);
        unpk(accp[i][1], v2, v3);
        float4 o;
        o.x = v0 + bi[0]; o.y = v1 + bi[1]; o.z = v2 + bi[2]; o.w = v3 + bi[3];
        *(float4*)&g_pre[(size_t)(bm + (ty << 2) + i) * G4n + bn + (tx << 2)] = o;
    }
}

// ---------------------------------------------------------------------------
// Kernel 2: persistent LSTM recurrence, 128 blocks (all resident).
// Block layout: half = blk>>6 (K-split: k in [half*512, half*512+512)),
//               p = blk&63 -> 16 hidden units (64 gate-cols), full batch 64.
// W_hh slice (64 gc x 512 k = 128KB) lives in smem for the ENTIRE kernel.
// Thread tile: 4 batch rows x 4 gates (one hidden unit), packed FFMA2.
// half=1 blocks write packed partials through L2; half=0 blocks combine,
// run the cell, and write h/out. One grid barrier per timestep.
// ---------------------------------------------------------------------------
#define HS_STRIDE 68
#define HS_BUF (32 * HS_STRIDE)            // floats per h chunk buffer
#define WS_FLOATS (KHALF * 64)             // 32768 floats = 128KB
#define LSTM_SMEM_FLOATS (WS_FLOATS + 2 * HS_BUF)
#define LSTM_SMEM_BYTES (LSTM_SMEM_FLOATS * 4)

__global__ void __launch_bounds__(256) lstm_seq_kernel(
    const float* __restrict__ Whh, float* __restrict__ out)
{
    extern __shared__ __align__(16) float dynsmem[];
    float* ws = dynsmem;                 // ws[k][gc] : k in [0,512), gc = nl*4+g
    float* hs = dynsmem + WS_FLOATS;     // hs[buf][k][row], stride 68, 64 rows

    const int tid = threadIdx.x;
    const int blk = blockIdx.x;
    const int half = blk >> 6;           // 0 = consumer (k low), 1 = producer (k high)
    const int p = blk & 63;
    const int n0 = p << 4;               // 16 hidden units
    const int k0 = half * KHALF;
    const int ty = tid >> 4;             // 0..15 -> rows 4ty..4ty+3
    const int tx = tid & 15;             // hidden unit within slice
    const int r0 = ty << 2;
    const int nn = n0 + tx;
    // h staging indices: row = tid>>2 (0..63), kb = tid&3; k-offsets kb+4j
    const int srow = tid >> 2;
    const int skb = tid & 3;

    // ---- one-time: load W slice into smem (gate-interleaved [k][nl*4+g]) ----
#pragma unroll 1
    for (int it = 0; it < 32; it++) {
        int f = (it * 256 + tid) << 2;   // flat float index into 64x512 slice
        int gc = f >> 9;                 // 512 floats per gate-col
        int k = f & 511;
        int g = gc & 3;
        int nl = gc >> 2;
        const float* src = Whh + (size_t)(g * Hn + n0 + nl) * Hn + k0 + k;
        float4 v = *(const float4*)src;
        ws[(k + 0) * 64 + gc] = v.x;
        ws[(k + 1) * 64 + gc] = v.y;
        ws[(k + 2) * 64 + gc] = v.z;
        ws[(k + 3) * 64 + gc] = v.w;
    }

    // ---- init: consumer zeroes its h0 slice, producer resets its flag ----
    if (half == 0) {
        int b = tid >> 2, nl4 = (tid & 3) << 2;
        float4 z = {0.f, 0.f, 0.f, 0.f};
        *(float4*)&g_hb[0][(size_t)b * Hn + n0 + nl4] = z;
    } else if (tid == 0) {
        *((volatile unsigned*)&g_flag[p]) = 0u;
    }
    float c[4] = {0.f, 0.f, 0.f, 0.f};
    grid_sync();

#pragma unroll 1
    for (int t = 0; t < Tn; t++) {
        const float* hr = g_hb[t & 1];
        float* hw = g_hb[(t + 1) & 1];
        const float* hbase = hr + (size_t)srow * Hn + k0 + skb;

        // accumulator init: consumer seeds from g_pre (input gates + bias)
        ull acc[4][2];
        if (half == 0) {
            const float* pp = g_pre + ((size_t)t * Bn + r0) * G4n + nn;
#pragma unroll
            for (int i = 0; i < 4; i++) {
                const float* q = pp + (size_t)i * G4n;
                acc[i][0] = pkab(q[0], q[Hn]);
                acc[i][1] = pkab(q[2 * Hn], q[3 * Hn]);
            }
        } else {
#pragma unroll
            for (int i = 0; i < 4; i++) { acc[i][0] = 0ull; acc[i][1] = 0ull; }
        }

        // stage h chunk 0 (k-offsets kb + 4j, transposed to [k][row])
        {
            float hv[8];
#pragma unroll
            for (int j = 0; j < 8; j++) hv[j] = __ldcg(hbase + 4 * j);
#pragma unroll
            for (int j = 0; j < 8; j++) hs[(skb + 4 * j) * HS_STRIDE + srow] = hv[j];
        }
        __syncthreads();

#pragma unroll 1
        for (int ch = 0; ch < 16; ch++) {
            float pv[8];
            if (ch < 15) {
                const float* nb = hbase + (ch + 1) * 32;
#pragma unroll
                for (int j = 0; j < 8; j++) pv[j] = __ldcg(nb + 4 * j);
            }
            const float* wsb = ws + (ch * 32) * 64;
            const float* hsb = hs + (ch & 1) * HS_BUF;
#pragma unroll
            for (int k = 0; k < 32; k++) {
                float4 a = *(const float4*)(hsb + k * HS_STRIDE + (ty << 2));
                ulonglong2 w = *(const ulonglong2*)(wsb + k * 64 + (tx << 2));
                ull a0 = pk2(a.x), a1 = pk2(a.y), a2 = pk2(a.z), a3 = pk2(a.w);
                fma2(acc[0][0], a0, w.x); fma2(acc[0][1], a0, w.y);
                fma2(acc[1][0], a1, w.x); fma2(acc[1][1], a1, w.y);
                fma2(acc[2][0], a2, w.x); fma2(acc[2][1], a2, w.y);
                fma2(acc[3][0], a3, w.x); fma2(acc[3][1], a3, w.y);
            }
            if (ch < 15) {
                float* d = hs + ((ch + 1) & 1) * HS_BUF;
#pragma unroll
                for (int j = 0; j < 8; j++) d[(skb + 4 * j) * HS_STRIDE + srow] = pv[j];
            }
            __syncthreads();
        }

        if (half == 1) {
            // producer: ship packed partials to consumer via L2, then flag
            ull* dst = &g_part[p][(size_t)tid * 8];
            st2cg(dst + 0, acc[0][0], acc[0][1]);
            st2cg(dst + 2, acc[1][0], acc[1][1]);
            st2cg(dst + 4, acc[2][0], acc[2][1]);
            st2cg(dst + 6, acc[3][0], acc[3][1]);
            __threadfence();
            __syncthreads();
            if (tid == 0) *((volatile unsigned*)&g_flag[p]) = (unsigned)(t + 1);
        } else {
            // consumer: wait for partner partials, combine, run the cell
            if (tid == 0) {
                while (*((volatile unsigned*)&g_flag[p]) < (unsigned)(t + 1)) __nanosleep(32);
                __threadfence();
            }
            __syncthreads();
            const ull* src = &g_part[p][(size_t)tid * 8];
            ull x0, x1;
            ld2cg(src + 0, x0, x1); add2(acc[0][0], x0); add2(acc[0][1], x1);
            ld2cg(src + 2, x0, x1); add2(acc[1][0], x0); add2(acc[1][1], x1);
            ld2cg(src + 4, x0, x1); add2(acc[2][0], x0); add2(acc[2][1], x1);
            ld2cg(src + 6, x0, x1); add2(acc[3][0], x0); add2(acc[3][1], x1);

#pragma unroll
            for (int i = 0; i < 4; i++) {
                float gi, gf, gg, go;
                unpk(acc[i][0], gi, gf);
                unpk(acc[i][1], gg, go);
                const float ig = sigf(gi);
                const float fg = sigf(gf);
                const float gv = tanhf(gg);
                const float og = sigf(go);
                const float cn = fg * c[i] + ig * gv;
                c[i] = cn;
                const float hval = og * tanhf(cn) * KEEP;
                const int b = r0 + i;
                __stcg(hw + (size_t)b * Hn + nn, hval);
                out[((size_t)t * Bn + b) * Hn + nn] = hval;
                if (t == Tn - 1) {
                    out[(size_t)Tn * Bn * Hn + (size_t)b * Hn + nn] = hval;                 // h_last
                    out[(size_t)Tn * Bn * Hn + (size_t)Bn * Hn + (size_t)b * Hn + nn] = cn; // c_last
                }
            }
        }
        grid_sync();
    }
}

extern "C" void kernel_launch(void* const* d_in, const int* in_sizes, int n_in,
                              void* d_out, int out_size) {
    const float* x   = (const float*)d_in[0];
    const float* Wih = (const float*)d_in[1];
    const float* Whh = (const float*)d_in[2];
    const float* bih = (const float*)d_in[3];
    const float* bhh = (const float*)d_in[4];
    float* out = (float*)d_out;

    cudaFuncSetAttribute(lstm_seq_kernel,
                         cudaFuncAttributeMaxDynamicSharedMemorySize, LSTM_SMEM_BYTES);

    dim3 g1(G4n / 64, (Tn * Bn) / 64);
    pre_gemm_kernel<<<g1, 256>>>(x, Wih, bih, bhh);
    lstm_seq_kernel<<<NBLK, 256, LSTM_SMEM_BYTES>>>(Whh, out);
}

// round 8
// speedup vs baseline: 1.2692x; 1.0458x over previous
#include <cuda_runtime.h>
#include <math.h>
#include <stdint.h>

#define Tn 512
#define Bn 64
#define In 512
#define Hn 1024
#define G4n 4096
#define KEEP 0.9f
#define NBLK 128
#define KHALF 512
#define CHUNK 128
#define NCH 4
#define HS_STRIDE 68
#define HS_BUF (CHUNK * HS_STRIDE)          // floats per h buffer
#define WS_FLOATS (KHALF * 64)              // 32768 floats = 128KB
#define LSTM_SMEM_FLOATS (WS_FLOATS + 2 * HS_BUF)
#define LSTM_SMEM_BYTES (LSTM_SMEM_FLOATS * 4)

typedef unsigned long long ull;

// Precomputed input-gates for all timesteps (T*B x 4H fp32 = 512MB)
__device__ float g_pre[(long long)Tn * Bn * G4n];
// Double-buffered hidden state, TRANSPOSED: [buf][k(=hidden unit)][batch row]
__device__ float g_hbT[2][Hn][Bn];
// Symmetric partial exchange: [writerHalf][pair][128 threads x 8 ull]
__device__ ull g_part2[2][64][128 * 8];
__device__ unsigned g_flag2[2][64];
// Grid barrier state (g_gen monotonic across graph replays)
__device__ unsigned g_count;
__device__ unsigned g_gen;

__device__ __forceinline__ float sigf(float x) { return 1.0f / (1.0f + expf(-x)); }

// ---- packed f32x2 helpers ----
__device__ __forceinline__ ull pk2(float v) {
    ull r; asm("mov.b64 %0, {%1, %1};" : "=l"(r) : "f"(v)); return r;
}
__device__ __forceinline__ ull pkab(float a, float b) {
    ull r; asm("mov.b64 %0, {%1, %2};" : "=l"(r) : "f"(a), "f"(b)); return r;
}
__device__ __forceinline__ void unpk(ull v, float& lo, float& hi) {
    asm("mov.b64 {%0, %1}, %2;" : "=f"(lo), "=f"(hi) : "l"(v));
}
__device__ __forceinline__ void fma2(ull& acc, ull a, ull b) {
    asm("fma.rn.f32x2 %0, %1, %2, %0;" : "+l"(acc) : "l"(a), "l"(b));
}
__device__ __forceinline__ void add2(ull& a, ull b) {
    asm("add.rn.f32x2 %0, %0, %1;" : "+l"(a) : "l"(b));
}
__device__ __forceinline__ void st2cg(ull* p, ull a, ull b) {
    asm volatile("st.global.cg.v2.u64 [%0], {%1, %2};" :: "l"(p), "l"(a), "l"(b) : "memory");
}
__device__ __forceinline__ void ld2cg(const ull* p, ull& a, ull& b) {
    asm volatile("ld.global.cg.v2.u64 {%0, %1}, [%2];" : "=l"(a), "=l"(b) : "l"(p) : "memory");
}
// cp.async 16B, L2 path (.cg) -> coherent with __stcg writers
__device__ __forceinline__ void cpa16(uint32_t dst, const float* src) {
    asm volatile("cp.async.cg.shared.global [%0], [%1], 16;" :: "r"(dst), "l"(src));
}
#define CP_COMMIT() asm volatile("cp.async.commit_group;" ::: "memory")
#define CP_WAIT0()  asm volatile("cp.async.wait_group 0;" ::: "memory")

__device__ __forceinline__ void grid_sync() {
    __threadfence();                 // release all prior global stores
    __syncthreads();
    if (threadIdx.x == 0) {
        volatile unsigned* vgen = &g_gen;
        unsigned gen = *vgen;
        if (atomicAdd(&g_count, 1u) == NBLK - 1) {
            g_count = 0u;
            __threadfence();
            atomicAdd(&g_gen, 1u);
        } else {
            while (*vgen == gen) { __nanosleep(32); }
        }
        __threadfence();             // acquire
    }
    __syncthreads();
}

// ---------------------------------------------------------------------------
// Kernel 1: G = (0.9*x) @ W_ih^T + (b_ih + b_hh), M=32768 N=4096 K=512.
// ---------------------------------------------------------------------------
__global__ void __launch_bounds__(256) pre_gemm_kernel(
    const float* __restrict__ x, const float* __restrict__ Wih,
    const float* __restrict__ bih, const float* __restrict__ bhh)
{
    __shared__ __align__(16) float As[2][16][64];
    __shared__ __align__(16) float Bs[2][16][64];
    const int tid = threadIdx.x;
    const int bm = blockIdx.y << 6;
    const int bn = blockIdx.x << 6;
    const int lm = tid >> 2;
    const int lk = (tid & 3) << 2;
    const int ty = tid >> 4;
    const int tx = tid & 15;

    const float* xrow = x + (size_t)(bm + lm) * In + lk;
    const float* wrow = Wih + (size_t)(bn + lm) * In + lk;

    {
        float4 av = *(const float4*)xrow;
        float4 wv = *(const float4*)wrow;
        As[0][lk + 0][lm] = av.x * KEEP; As[0][lk + 1][lm] = av.y * KEEP;
        As[0][lk + 2][lm] = av.z * KEEP; As[0][lk + 3][lm] = av.w * KEEP;
        Bs[0][lk + 0][lm] = wv.x; Bs[0][lk + 1][lm] = wv.y;
        Bs[0][lk + 2][lm] = wv.z; Bs[0][lk + 3][lm] = wv.w;
    }
    __syncthreads();

    ull accp[4][2];
#pragma unroll
    for (int i = 0; i < 4; i++) { accp[i][0] = 0ull; accp[i][1] = 0ull; }

#pragma unroll 1
    for (int ch = 0; ch < 32; ch++) {
        const int buf = ch & 1;
        float4 a2, w2;
        if (ch < 31) {
            a2 = *(const float4*)(xrow + (ch + 1) * 16);
            w2 = *(const float4*)(wrow + (ch + 1) * 16);
        }
#pragma unroll
        for (int k = 0; k < 16; k++) {
            float4 a = *(const float4*)&As[buf][k][ty << 2];
            ulonglong2 w = *(const ulonglong2*)&Bs[buf][k][tx << 2];
            ull a0 = pk2(a.x), a1 = pk2(a.y), a2p = pk2(a.z), a3 = pk2(a.w);
            fma2(accp[0][0], a0, w.x); fma2(accp[0][1], a0, w.y);
            fma2(accp[1][0], a1, w.x); fma2(accp[1][1], a1, w.y);
            fma2(accp[2][0], a2p, w.x); fma2(accp[2][1], a2p, w.y);
            fma2(accp[3][0], a3, w.x); fma2(accp[3][1], a3, w.y);
        }
        if (ch < 31) {
            const int nb = buf ^ 1;
            As[nb][lk + 0][lm] = a2.x * KEEP; As[nb][lk + 1][lm] = a2.y * KEEP;
            As[nb][lk + 2][lm] = a2.z * KEEP; As[nb][lk + 3][lm] = a2.w * KEEP;
            Bs[nb][lk + 0][lm] = w2.x; Bs[nb][lk + 1][lm] = w2.y;
            Bs[nb][lk + 2][lm] = w2.z; Bs[nb][lk + 3][lm] = w2.w;
        }
        __syncthreads();
    }

    float bi[4];
#pragma unroll
    for (int j = 0; j < 4; j++) {
        int col = bn + (tx << 2) + j;
        bi[j] = bih[col] + bhh[col];
    }
#pragma unroll
    for (int i = 0; i < 4; i++) {
        float v0, v1, v2, v3;
        unpk(accp[i][0], v0, v1);
        unpk(accp[i][1], v2, v3);
        float4 o;
        o.x = v0 + bi[0]; o.y = v1 + bi[1]; o.z = v2 + bi[2]; o.w = v3 + bi[3];
        *(float4*)&g_pre[(size_t)(bm + (ty << 2) + i) * G4n + bn + (tx << 2)] = o;
    }
}

// ---------------------------------------------------------------------------
// Kernel 2: persistent LSTM recurrence, 128 blocks, symmetric K-split pairs.
// blk = 2p + half; half owns k in [half*512, half*512+512) and batch rows
// [half*32, half*32+32). W slice (64 gc x 512 k = 128KB) resident in smem.
// h stored transposed in global: g_hbT[buf][unit][row]; staged via cp.async
// in 128-k double-buffered chunks (4 syncs/step). Partial exchange through
// L2 is symmetric (each block ships only the partner-owned 32 rows).
// ---------------------------------------------------------------------------
__global__ void __launch_bounds__(256) lstm_seq_kernel(
    const float* __restrict__ Whh, float* __restrict__ out)
{
    extern __shared__ __align__(16) float dynsmem[];
    float* ws = dynsmem;                 // ws[k][gc], k in [0,512), gc = nl*4+g
    float* hs = dynsmem + WS_FLOATS;     // hs[buf][k][row], stride HS_STRIDE
    const uint32_t hs_sm = (uint32_t)__cvta_generic_to_shared(hs);

    const int tid = threadIdx.x;
    const int blk = blockIdx.x;
    const int p = blk >> 1;
    const int half = blk & 1;
    const int n0 = p << 4;               // 16 hidden units
    const int k0 = half * KHALF;
    const int ty = tid >> 4;             // 0..15 -> rows 4ty..4ty+3
    const int tx = tid & 15;             // hidden unit within slice
    const int r0 = ty << 2;
    const int nn = n0 + tx;
    const bool own = ((ty >> 3) == half);   // this thread's rows belong to my half
    const int xslot = ((ty & 7) * 16 + tx) * 8;
    // staging indices
    const int r4 = (tid & 15) << 2;      // row quad base (0,4,..,60)
    const int kb = (tid >> 4) << 3;      // k base (0,8,..,120)

    // ---- one-time: W slice -> smem, gate-interleaved [k][nl*4+g] ----
#pragma unroll 1
    for (int it = 0; it < 32; it++) {
        int f = (it * 256 + tid) << 2;
        int gc = f >> 9;
        int k = f & 511;
        int g = gc & 3;
        int nl = gc >> 2;
        const float* src = Whh + (size_t)(g * Hn + n0 + nl) * Hn + k0 + k;
        float4 v = *(const float4*)src;
        ws[(k + 0) * 64 + gc] = v.x;
        ws[(k + 1) * 64 + gc] = v.y;
        ws[(k + 2) * 64 + gc] = v.z;
        ws[(k + 3) * 64 + gc] = v.w;
    }

    // ---- init: p==0 blocks zero hT buffer 0 (their k-half); reset flags ----
    if (p == 0) {
        float4 z = {0.f, 0.f, 0.f, 0.f};
        float4* hb0 = (float4*)&g_hbT[0][k0][0];
#pragma unroll
        for (int m = 0; m < 32; m++) hb0[m * 256 + tid] = z;
    }
    if (tid == 0) *((volatile unsigned*)&g_flag2[half][p]) = 0u;
    float c[4] = {0.f, 0.f, 0.f, 0.f};
    grid_sync();

#pragma unroll 1
    for (int t = 0; t < Tn; t++) {
        const float* hsrc = &g_hbT[t & 1][k0][0];

        // seeds (input gates + bias) for own rows; loads overlap the GEMM
        float sd[16];
        if (own) {
            const float* q = g_pre + ((size_t)t * Bn + r0) * G4n + nn;
#pragma unroll
            for (int i = 0; i < 4; i++) {
                sd[i * 4 + 0] = q[(size_t)i * G4n];
                sd[i * 4 + 1] = q[(size_t)i * G4n + Hn];
                sd[i * 4 + 2] = q[(size_t)i * G4n + 2 * Hn];
                sd[i * 4 + 3] = q[(size_t)i * G4n + 3 * Hn];
            }
        }

        ull acc[4][2];
#pragma unroll
        for (int i = 0; i < 4; i++) { acc[i][0] = 0ull; acc[i][1] = 0ull; }

        // preload chunk 0
        {
            const float* s0 = hsrc;
#pragma unroll
            for (int j = 0; j < 8; j++) {
                int k = kb + j;
                cpa16(hs_sm + (uint32_t)(k * HS_STRIDE + r4) * 4, s0 + k * 64 + r4);
            }
            CP_COMMIT();
        }

#pragma unroll 1
        for (int ch = 0; ch < NCH; ch++) {
            CP_WAIT0();
            __syncthreads();
            if (ch < NCH - 1) {
                const int nb = (ch + 1) & 1;
                const float* s1 = hsrc + (ch + 1) * CHUNK * 64;
#pragma unroll
                for (int j = 0; j < 8; j++) {
                    int k = kb + j;
                    cpa16(hs_sm + (uint32_t)(nb * HS_BUF + k * HS_STRIDE + r4) * 4,
                          s1 + k * 64 + r4);
                }
                CP_COMMIT();
            }
            const float* hsb = hs + (ch & 1) * HS_BUF;
            const float* wsb = ws + (size_t)ch * CHUNK * 64;
#pragma unroll 8
            for (int k = 0; k < CHUNK; k++) {
                float4 a = *(const float4*)(hsb + k * HS_STRIDE + r0);
                ulonglong2 w = *(const ulonglong2*)(wsb + k * 64 + (tx << 2));
                ull a0 = pk2(a.x), a1 = pk2(a.y), a2 = pk2(a.z), a3 = pk2(a.w);
                fma2(acc[0][0], a0, w.x); fma2(acc[0][1], a0, w.y);
                fma2(acc[1][0], a1, w.x); fma2(acc[1][1], a1, w.y);
                fma2(acc[2][0], a2, w.x); fma2(acc[2][1], a2, w.y);
                fma2(acc[3][0], a3, w.x); fma2(acc[3][1], a3, w.y);
            }
        }

        // ---- symmetric exchange: ship partner-owned rows' partials ----
        if (!own) {
            ull* dst = &g_part2[half][p][xslot];
            st2cg(dst + 0, acc[0][0], acc[0][1]);
            st2cg(dst + 2, acc[1][0], acc[1][1]);
            st2cg(dst + 4, acc[2][0], acc[2][1]);
            st2cg(dst + 6, acc[3][0], acc[3][1]);
        }
        __threadfence();
        __syncthreads();
        if (tid == 0) {
            *((volatile unsigned*)&g_flag2[half][p]) = (unsigned)(t + 1);
            while (*((volatile unsigned*)&g_flag2[half ^ 1][p]) < (unsigned)(t + 1))
                __nanosleep(32);
            __threadfence();
        }
        __syncthreads();

        // ---- combine + cell for own rows ----
        if (own) {
            const ull* src = &g_part2[half ^ 1][p][xslot];
            ull x0, x1;
            ld2cg(src + 0, x0, x1); add2(acc[0][0], x0); add2(acc[0][1], x1);
            ld2cg(src + 2, x0, x1); add2(acc[1][0], x0); add2(acc[1][1], x1);
            ld2cg(src + 4, x0, x1); add2(acc[2][0], x0); add2(acc[2][1], x1);
            ld2cg(src + 6, x0, x1); add2(acc[3][0], x0); add2(acc[3][1], x1);

            float4 hq;
#pragma unroll
            for (int i = 0; i < 4; i++) {
                add2(acc[i][0], pkab(sd[i * 4 + 0], sd[i * 4 + 1]));
                add2(acc[i][1], pkab(sd[i * 4 + 2], sd[i * 4 + 3]));
                float gi, gf, gg, go;
                unpk(acc[i][0], gi, gf);
                unpk(acc[i][1], gg, go);
                const float ig = sigf(gi);
                const float fg = sigf(gf);
                const float gv = tanhf(gg);
                const float og = sigf(go);
                const float cn = fg * c[i] + ig * gv;
                c[i] = cn;
                const float hval = og * tanhf(cn) * KEEP;
                ((float*)&hq)[i] = hval;
                const int b = r0 + i;
                out[((size_t)t * Bn + b) * Hn + nn] = hval;
                if (t == Tn - 1) {
                    out[(size_t)Tn * Bn * Hn + (size_t)b * Hn + nn] = hval;                 // h_last
                    out[(size_t)Tn * Bn * Hn + (size_t)Bn * Hn + (size_t)b * Hn + nn] = cn; // c_last
                }
            }
            __stcg((float4*)&g_hbT[(t + 1) & 1][nn][r0], hq);
        }
        grid_sync();
    }
}

extern "C" void kernel_launch(void* const* d_in, const int* in_sizes, int n_in,
                              void* d_out, int out_size) {
    const float* x   = (const float*)d_in[0];
    const float* Wih = (const float*)d_in[1];
    const float* Whh = (const float*)d_in[2];
    const float* bih = (const float*)d_in[3];
    const float* bhh = (const float*)d_in[4];
    float* out = (float*)d_out;

    cudaFuncSetAttribute(lstm_seq_kernel,
                         cudaFuncAttributeMaxDynamicSharedMemorySize, LSTM_SMEM_BYTES);

    dim3 g1(G4n / 64, (Tn * Bn) / 64);
    pre_gemm_kernel<<<g1, 256>>>(x, Wih, bih, bhh);
    lstm_seq_kernel<<<NBLK, 256, LSTM_SMEM_BYTES>>>(Whh, out);
}